// round 2
// baseline (speedup 1.0000x reference)
#include <cuda_runtime.h>
#include <cuda_fp16.h>

#define FEAT 4096
#define TT   2048
#define ODIM 512
#define NCTA 148
#define NTHREADS 1024
#define SMEMB (28 * FEAT * 2)   // 28 rows of fp16 weights = 229376 bytes

// Static device scratch (no runtime allocation allowed)
__device__ __half   d_Wh[(size_t)FEAT * FEAT];      // fp16 copy of W_res, 33.5 MB
__device__ float    d_G[(size_t)(TT + 1) * FEAT];   // feats history, G[t][f], 33.6 MB
__device__ unsigned d_cnt[TT];                      // per-step arrival counters

// ---------------------------------------------------------------------------
// fp32 -> fp16 weight conversion
// ---------------------------------------------------------------------------
__global__ void convert_kernel(const float* __restrict__ W) {
    size_t n = (size_t)FEAT * FEAT / 4;
    for (size_t i = blockIdx.x * (size_t)blockDim.x + threadIdx.x; i < n;
         i += (size_t)gridDim.x * blockDim.x) {
        float4 v = reinterpret_cast<const float4*>(W)[i];
        __half2 h0 = __floats2half2_rn(v.x, v.y);
        __half2 h1 = __floats2half2_rn(v.z, v.w);
        uint2 u;
        u.x = *reinterpret_cast<unsigned*>(&h0);
        u.y = *reinterpret_cast<unsigned*>(&h1);
        reinterpret_cast<uint2*>(d_Wh)[i] = u;
    }
}

// ---------------------------------------------------------------------------
// Sync primitives
// ---------------------------------------------------------------------------
__device__ __forceinline__ unsigned ld_acq(const unsigned* p) {
    unsigned v;
    asm volatile("ld.acquire.gpu.global.u32 %0, [%1];" : "=r"(v) : "l"(p) : "memory");
    return v;
}
__device__ __forceinline__ void red_rel_add1(unsigned* p) {
    asm volatile("red.release.gpu.global.add.u32 [%0], 1;" :: "l"(p) : "memory");
}

// ---------------------------------------------------------------------------
// Persistent recurrence kernel: 148 CTAs, each owns <=28 rows of W in SMEM.
// Step t: y = W_slice @ G[t] (+x[:,t]), clamp, write G[t+1] slice, signal.
// Warp layout: 32 warps = 4 row-groups x 8 k-groups.
//   warp w: rg = w&3 (rows rg*7..rg*7+6), kg = w>>2 (k in [kg*512, kg*512+512))
//   lane l: 4 sub-chunks of 4 contiguous elems at c = kg*512 + s*128 + l*4
// ---------------------------------------------------------------------------
extern "C" __global__ void __launch_bounds__(NTHREADS, 1)
rc_kernel(const float* __restrict__ x) {
    extern __shared__ __half sW[];            // [nrows][FEAT]
    __shared__ float sPart[28][8];

    const int b   = blockIdx.x;
    const int tid = threadIdx.x;

    // Row distribution: first 100 CTAs get 28 rows, last 48 get 27 (=4096).
    int r0, nrows;
    if (b < 100) { r0 = b * 28;              nrows = 28; }
    else         { r0 = 2800 + (b - 100) * 27; nrows = 27; }

    // Stage W slice into SMEM (once)
    {
        const uint4* wg = reinterpret_cast<const uint4*>(d_Wh + (size_t)r0 * FEAT);
        uint4* ws = reinterpret_cast<uint4*>(sW);
        int nv = nrows * FEAT / 8;            // uint4 = 8 halfs
        for (int i = tid; i < nv; i += NTHREADS) ws[i] = wg[i];
    }
    __syncthreads();

    const int w    = tid >> 5;
    const int lane = tid & 31;
    const int rg   = w & 3;
    const int kg   = w >> 2;
    const int rbeg = rg * 7;
    const int rend = min(rbeg + 7, nrows);
    const int cb   = kg * 512 + lane * 4;

    for (int t = 0; t < TT; ++t) {
        // Prefetch x[:, t] for this CTA's rows (independent of the barrier)
        float xv = 0.f;
        if (tid < nrows) xv = __ldg(&x[(size_t)(r0 + tid) * TT + t]);

        if (t > 0) {
            if (tid == 0) {
                while (ld_acq(&d_cnt[t - 1]) < NCTA) { }
            }
            __syncthreads();
        }

        const float* f = d_G + (size_t)t * FEAT;
        float4 f0 = __ldcg(reinterpret_cast<const float4*>(f + cb));
        float4 f1 = __ldcg(reinterpret_cast<const float4*>(f + cb + 128));
        float4 f2 = __ldcg(reinterpret_cast<const float4*>(f + cb + 256));
        float4 f3 = __ldcg(reinterpret_cast<const float4*>(f + cb + 384));

        float acc[7];
        #pragma unroll
        for (int j = 0; j < 7; ++j) acc[j] = 0.f;

        #pragma unroll
        for (int j = 0; j < 7; ++j) {
            int r = rbeg + j;
            if (r < rend) {
                const __half* wr = sW + (size_t)r * FEAT + cb;
                uint2 ha = *reinterpret_cast<const uint2*>(wr);
                uint2 hb = *reinterpret_cast<const uint2*>(wr + 128);
                uint2 hc = *reinterpret_cast<const uint2*>(wr + 256);
                uint2 hd = *reinterpret_cast<const uint2*>(wr + 384);
                float2 a0 = __half22float2(*reinterpret_cast<__half2*>(&ha.x));
                float2 a1 = __half22float2(*reinterpret_cast<__half2*>(&ha.y));
                float2 b0 = __half22float2(*reinterpret_cast<__half2*>(&hb.x));
                float2 b1 = __half22float2(*reinterpret_cast<__half2*>(&hb.y));
                float2 c0 = __half22float2(*reinterpret_cast<__half2*>(&hc.x));
                float2 c1 = __half22float2(*reinterpret_cast<__half2*>(&hc.y));
                float2 d0 = __half22float2(*reinterpret_cast<__half2*>(&hd.x));
                float2 d1 = __half22float2(*reinterpret_cast<__half2*>(&hd.y));
                float s = 0.f;
                s = fmaf(a0.x, f0.x, s); s = fmaf(a0.y, f0.y, s);
                s = fmaf(a1.x, f0.z, s); s = fmaf(a1.y, f0.w, s);
                s = fmaf(b0.x, f1.x, s); s = fmaf(b0.y, f1.y, s);
                s = fmaf(b1.x, f1.z, s); s = fmaf(b1.y, f1.w, s);
                s = fmaf(c0.x, f2.x, s); s = fmaf(c0.y, f2.y, s);
                s = fmaf(c1.x, f2.z, s); s = fmaf(c1.y, f2.w, s);
                s = fmaf(d0.x, f3.x, s); s = fmaf(d0.y, f3.y, s);
                s = fmaf(d1.x, f3.z, s); s = fmaf(d1.y, f3.w, s);
                acc[j] = s;
            }
        }

        // Warp reduction over 32 lanes for each of this warp's rows
        #pragma unroll
        for (int j = 0; j < 7; ++j) {
            float v = acc[j];
            v += __shfl_down_sync(0xFFFFFFFFu, v, 16);
            v += __shfl_down_sync(0xFFFFFFFFu, v, 8);
            v += __shfl_down_sync(0xFFFFFFFFu, v, 4);
            v += __shfl_down_sync(0xFFFFFFFFu, v, 2);
            v += __shfl_down_sync(0xFFFFFFFFu, v, 1);
            if (lane == 0 && rbeg + j < rend) sPart[rbeg + j][kg] = v;
        }
        __syncthreads();

        if (tid < nrows) {
            float s = 0.f;
            #pragma unroll
            for (int k = 0; k < 8; ++k) s += sPart[tid][k];
            s += xv;
            s = fminf(fmaxf(s, -1.f), 1.f);
            d_G[(size_t)(t + 1) * FEAT + r0 + tid] = s;
            __threadfence();
        }
        __syncthreads();
        if (tid == 0) red_rel_add1(&d_cnt[t]);
    }
}

// ---------------------------------------------------------------------------
// Readout GEMM: out[o][t] = sum_f w_out[o][f] * G[t+1][f]
// 64x64 tile per block, BK=32, 256 threads, 4x4 micro-tile per thread.
// ---------------------------------------------------------------------------
__global__ void __launch_bounds__(256)
out_gemm(const float* __restrict__ wout, float* __restrict__ out) {
    __shared__ float As[32][65];   // As[k][i]  (i: out rows)
    __shared__ float Bs[32][65];   // Bs[k][j]  (j: timesteps)

    const int t0 = blockIdx.x * 64;
    const int o0 = blockIdx.y * 64;
    const int tid = threadIdx.x;
    const int tx = tid & 15, ty = tid >> 4;

    float c[4][4];
    #pragma unroll
    for (int p = 0; p < 4; ++p)
        #pragma unroll
        for (int q = 0; q < 4; ++q) c[p][q] = 0.f;

    for (int k0 = 0; k0 < FEAT; k0 += 32) {
        // load A tile: 64x32 (2048 floats -> 2x 256 threads x float4)
        #pragma unroll
        for (int it = 0; it < 2; ++it) {
            int idx = it * 256 + tid;          // 0..511
            int i  = idx >> 3;                 // 0..63
            int kv = (idx & 7) * 4;            // 0,4,..28
            float4 v = *reinterpret_cast<const float4*>(
                &wout[(size_t)(o0 + i) * FEAT + k0 + kv]);
            As[kv + 0][i] = v.x; As[kv + 1][i] = v.y;
            As[kv + 2][i] = v.z; As[kv + 3][i] = v.w;
        }
        // load B tile: Bs[k][j] = G[(t0+j+1)*FEAT + k0+k]
        #pragma unroll
        for (int it = 0; it < 2; ++it) {
            int idx = it * 256 + tid;
            int j  = idx >> 3;
            int kv = (idx & 7) * 4;
            float4 v = *reinterpret_cast<const float4*>(
                &d_G[(size_t)(t0 + j + 1) * FEAT + k0 + kv]);
            Bs[kv + 0][j] = v.x; Bs[kv + 1][j] = v.y;
            Bs[kv + 2][j] = v.z; Bs[kv + 3][j] = v.w;
        }
        __syncthreads();

        #pragma unroll
        for (int kk = 0; kk < 32; ++kk) {
            float a[4], bb[4];
            #pragma unroll
            for (int p = 0; p < 4; ++p) a[p] = As[kk][ty * 4 + p];
            #pragma unroll
            for (int q = 0; q < 4; ++q) bb[q] = Bs[kk][tx * 4 + q];
            #pragma unroll
            for (int p = 0; p < 4; ++p)
                #pragma unroll
                for (int q = 0; q < 4; ++q)
                    c[p][q] = fmaf(a[p], bb[q], c[p][q]);
        }
        __syncthreads();
    }

    #pragma unroll
    for (int p = 0; p < 4; ++p)
        #pragma unroll
        for (int q = 0; q < 4; ++q)
            out[(size_t)(o0 + ty * 4 + p) * TT + t0 + tx * 4 + q] = c[p][q];
}

// ---------------------------------------------------------------------------
extern "C" void kernel_launch(void* const* d_in, const int* in_sizes, int n_in,
                              void* d_out, int out_size) {
    const float* x    = (const float*)d_in[0];   // [4096, 2048]
    const float* Wres = (const float*)d_in[1];   // [4096, 4096]
    const float* wout = (const float*)d_in[2];   // [512, 4096]
    float* out = (float*)d_out;                  // [512, 2048]

    cudaFuncSetAttribute(rc_kernel, cudaFuncAttributeMaxDynamicSharedMemorySize, SMEMB);

    void* cntp = nullptr;
    void* gp   = nullptr;
    cudaGetSymbolAddress(&cntp, d_cnt);
    cudaGetSymbolAddress(&gp, d_G);
    cudaMemsetAsync(cntp, 0, TT * sizeof(unsigned));   // reset step counters
    cudaMemsetAsync(gp, 0, FEAT * sizeof(float));      // feats_0 = 0

    convert_kernel<<<1024, 256>>>(Wres);
    rc_kernel<<<NCTA, NTHREADS, SMEMB>>>(x);
    out_gemm<<<dim3(TT / 64, ODIM / 64), 256>>>(wout, out);
}